// round 8
// baseline (speedup 1.0000x reference)
#include <cuda_runtime.h>
#include <math.h>

#define NBLK 128
#define NTHR 512
#define H    256
#define HE   64
#define APER 64
#define NPER 512
#define EPSF 1e-8f
#define INFM 1000000.0f
#define MU_STEP (20.0f/63.0f)
#define INV_SIG (64.0f/20.0f)

typedef unsigned long long u64;

// ------------------------- scratch (device globals) --------------------------
__device__ float g_wc [2*256*320];
__device__ float g_aux[640];          // [0:256) wqbk, [256:576) biasc, [576] bq.bk
__device__ float g_qke[2*512*320];
__device__ float g_cb [512*320];      // [n_tilde | s]
__device__ float g_upd[4*512*256];
__device__ float g_af [512*256];
__device__ float g_m1 [2*512*512];
__device__ float g_m2 [2*512*512];
__device__ float g_m3 [4*512*256];

__device__ unsigned g_bar_count = 0;
__device__ unsigned g_bar_epoch = 0;

// ------------------------- f32x2 helpers --------------------------------------
__device__ __forceinline__ void ffma2(u64 &d, u64 a, u64 b){
  asm("fma.rn.f32x2 %0, %1, %2, %0;" : "+l"(d) : "l"(a), "l"(b));
}
__device__ __forceinline__ u64 pack2(float x, float y){
  u64 r; asm("mov.b64 %0, {%1, %2};" : "=l"(r) : "f"(x), "f"(y)); return r;
}
__device__ __forceinline__ float2 unpack2(u64 v){
  float2 r; asm("mov.b64 {%0, %1}, %2;" : "=f"(r.x), "=f"(r.y) : "l"(v)); return r;
}

// ------------------------- reductions ------------------------------------------
__device__ __forceinline__ float warp_reduce_sum(float v){
#pragma unroll
  for (int o=16;o>0;o>>=1) v += __shfl_xor_sync(0xffffffffu, v, o);
  return v;
}
__device__ __forceinline__ float warp_reduce_max(float v){
#pragma unroll
  for (int o=16;o>0;o>>=1) v = fmaxf(v, __shfl_xor_sync(0xffffffffu, v, o));
  return v;
}

// Software grid barrier (all NBLK blocks co-resident by construction).
__device__ __forceinline__ void grid_barrier(){
  __syncthreads();
  if (threadIdx.x == 0){
    __threadfence();
    unsigned e = atomicAdd(&g_bar_epoch, 0u);
    unsigned prev = atomicAdd(&g_bar_count, 1u);
    if (prev == gridDim.x - 1){
      atomicExch(&g_bar_count, 0u);
      __threadfence();
      atomicAdd(&g_bar_epoch, 1u);
    } else {
      volatile unsigned* ep = (volatile unsigned*)&g_bar_epoch;
      while (*ep == e) { }
      __threadfence();
    }
  }
  __syncthreads();
}

// ------------------------- shared memory ----------------------------------------
struct GemmSmem { float As[2][16][68]; u64 Bs[2][16][66]; };
struct AttnA    { float qk[4][H]; float qek[4][HE]; float logit[4][NPER]; };
union  __align__(16) SU { GemmSmem g; AttnA a; };

// ------------------------- GEMM 64x64 tile, 512 threads, f32x2 ------------------
// A_KM: A is K-major (A[k*lda+m]); else row-major.
// ASUM: A := relu(A + A2 + abias[col k]) on load (partial-sum consumption).
// B_KN: B is (K,N) row-major; else (N,K) row-major. BSUM: B += B2 on load.
template<bool A_KM, bool ASUM, bool B_KN, bool BSUM>
__device__ void gemm64(const float* __restrict__ A, int lda,
                       const float* __restrict__ A2,
                       const float* __restrict__ abias,
                       const float* __restrict__ B, int ldb,
                       const float* __restrict__ B2,
                       float* __restrict__ C, int ldc,
                       int m0, int n0, int kbeg, int kend,
                       GemmSmem* sm)
{
  const int tid = threadIdx.x;
  const int tx = tid & 15, ty = tid >> 4;      // ty 0..31 (m-pairs), tx (n-grp)
  const bool isA = tid < 256;
  const int t = isA ? tid : tid - 256;
  int a_i0, a_i1, b_i0, b_i1;
  if (A_KM){ a_i0 = t >> 4; a_i1 = t & 15; }   // k-row, m-grp
  else     { a_i0 = t >> 2; a_i1 = t & 3;  }   // m-row, k-grp
  if (B_KN){ b_i0 = t >> 4; b_i1 = t & 15; }   // k-row, n-grp
  else     { b_i0 = t >> 2; b_i1 = t & 3;  }   // n-row, k-grp

  auto fetch = [&](int k0)->float4 {
    if (isA){
      if (A_KM)
        return *(const float4*)(A + (size_t)(k0 + a_i0)*lda + m0 + a_i1*4);
      const size_t o = (size_t)(m0 + a_i0)*lda + k0 + a_i1*4;
      float4 v = *(const float4*)(A + o);
      if (ASUM){
        float4 v2 = *(const float4*)(A2 + o);
        float4 vb = *(const float4*)(abias + k0 + a_i1*4);
        v.x = fmaxf(v.x+v2.x+vb.x, 0.f); v.y = fmaxf(v.y+v2.y+vb.y, 0.f);
        v.z = fmaxf(v.z+v2.z+vb.z, 0.f); v.w = fmaxf(v.w+v2.w+vb.w, 0.f);
      }
      return v;
    } else {
      if (B_KN){
        const size_t o = (size_t)(k0 + b_i0)*ldb + n0 + b_i1*4;
        float4 v = *(const float4*)(B + o);
        if (BSUM){
          float4 w = *(const float4*)(B2 + o);
          v.x+=w.x; v.y+=w.y; v.z+=w.z; v.w+=w.w;
        }
        return v;
      }
      return *(const float4*)(B + (size_t)(n0 + b_i0)*ldb + k0 + b_i1*4);
    }
  };
  auto stage = [&](int buf, float4 v){
    if (isA){
      if (A_KM) *(float4*)&sm->As[buf][a_i0][a_i1*4] = v;
      else {
        sm->As[buf][a_i1*4+0][a_i0] = v.x;
        sm->As[buf][a_i1*4+1][a_i0] = v.y;
        sm->As[buf][a_i1*4+2][a_i0] = v.z;
        sm->As[buf][a_i1*4+3][a_i0] = v.w;
      }
    } else {
      u64 p0 = pack2(v.x,v.x), p1 = pack2(v.y,v.y);
      u64 p2 = pack2(v.z,v.z), p3 = pack2(v.w,v.w);
      if (B_KN){
        ulonglong2* dst = (ulonglong2*)&sm->Bs[buf][b_i0][b_i1*4];
        dst[0] = make_ulonglong2(p0,p1);
        dst[1] = make_ulonglong2(p2,p3);
      } else {
        sm->Bs[buf][b_i1*4+0][b_i0] = p0;
        sm->Bs[buf][b_i1*4+1][b_i0] = p1;
        sm->Bs[buf][b_i1*4+2][b_i0] = p2;
        sm->Bs[buf][b_i1*4+3][b_i0] = p3;
      }
    }
  };

  u64 acc0=0ULL, acc1=0ULL, acc2=0ULL, acc3=0ULL;
  __syncthreads();                    // protect smem union reuse
  stage(0, fetch(kbeg));
  __syncthreads();
  int buf = 0;
  for (int k0 = kbeg + 16;; k0 += 16){
    const bool more = (k0 < kend);
    float4 nv;
    if (more) nv = fetch(k0);
#pragma unroll
    for (int kk = 0; kk < 16; kk++){
      u64 a = *(const u64*)&sm->As[buf][kk][ty*2];
      ulonglong2 b01 = *(const ulonglong2*)&sm->Bs[buf][kk][tx*4];
      ulonglong2 b23 = *(const ulonglong2*)&sm->Bs[buf][kk][tx*4+2];
      ffma2(acc0, a, b01.x); ffma2(acc1, a, b01.y);
      ffma2(acc2, a, b23.x); ffma2(acc3, a, b23.y);
    }
    if (!more) break;
    stage(buf^1, nv);
    __syncthreads();
    buf ^= 1;
  }
  float2 c0 = unpack2(acc0), c1 = unpack2(acc1);
  float2 c2 = unpack2(acc2), c3 = unpack2(acc3);
  const int m = m0 + ty*2;
  *(float4*)(C + (size_t)m*ldc + n0 + tx*4)     = make_float4(c0.x,c1.x,c2.x,c3.x);
  *(float4*)(C + (size_t)(m+1)*ldc + n0 + tx*4) = make_float4(c0.y,c1.y,c2.y,c3.y);
}

// ------------------------- residual + LN (4 rows/block, P partials) -------------
template<int P>
__device__ void lnP(const float* __restrict__ r,
                    const float* __restrict__ part, size_t pstride,
                    const float* __restrict__ bias,
                    const float* __restrict__ g, const float* __restrict__ b,
                    float* __restrict__ o)
{
  const int w = threadIdx.x >> 5, lane = threadIdx.x & 31;
  if (w >= 4) return;
  const size_t row = (size_t)blockIdx.x*4 + w;
  float v[8]; float s = 0.f;
#pragma unroll
  for (int i=0;i<8;i++){
    int c = lane + i*32;
    size_t idx = row*H + c;
    float x = r[idx] + bias[c];
#pragma unroll
    for (int p=0;p<P;p++) x += part[(size_t)p*pstride + idx];
    v[i] = x; s += x;
  }
  s = warp_reduce_sum(s);
  float mean = s * (1.f/H);
  float s2 = 0.f;
#pragma unroll
  for (int i=0;i<8;i++){ float d = v[i]-mean; s2 += d*d; }
  s2 = warp_reduce_sum(s2);
  float inv = rsqrtf(s2*(1.f/H) + 1e-5f);
#pragma unroll
  for (int i=0;i<8;i++){
    int c = lane + i*32;
    o[row*H+c] = (v[i]-mean)*inv*g[c] + b[c];
  }
}

// ------------------------- megakernel -------------------------------------------
__global__ __launch_bounds__(NTHR)
void mega(const float* __restrict__ anchor_x,
          const float* __restrict__ node_x,
          const float* __restrict__ afeat,
          const float* __restrict__ nf,
          const float* __restrict__ nmask,
          const float* __restrict__ Wq,  const float* __restrict__ bq,
          const float* __restrict__ Wkv, const float* __restrict__ bkv,
          const float* __restrict__ ln1g, const float* __restrict__ ln1b,
          const float* __restrict__ W1, const float* __restrict__ b1,
          const float* __restrict__ W2, const float* __restrict__ b2,
          const float* __restrict__ W3, const float* __restrict__ b3,
          const float* __restrict__ ln2g, const float* __restrict__ ln2b,
          float* __restrict__ out)
{
  __shared__ SU su;
  __shared__ __align__(16) float s_dist[4][NPER];
  __shared__ float s_ax[4][3];
  __shared__ float s_qbk[4];
  __shared__ int   s_list[NPER];
  __shared__ int   s_cnt;
  __shared__ float s_red[16];

  const int tid = threadIdx.x, bid = blockIdx.x;
  const int lane = tid & 31, warp = tid >> 5;
  const int a0 = bid*4;
  const int nbase = (a0 / APER) * NPER;

  // ========== stage A: wc partials (split-K 2) + aux vectors ==================
  if (bid < 40){
    int z = bid/20, tt = bid%20, my = tt/5, nx = tt%5;
    gemm64<true,false,true,false>(Wq,256, nullptr,nullptr, Wkv,320, nullptr,
        g_wc + (size_t)z*81920, 320, my*64, nx*64, z*128, z*128+128, &su.g);
  } else if (bid == 40){
    for (int i = tid; i < 256; i += NTHR){
      float s = 0.f;
      for (int j = 0; j < 256; j++) s = fmaf(Wq[(size_t)j*256 + i], bkv[j], s);
      g_aux[i] = s;
    }
  } else if (bid == 41){
    for (int c = tid; c < 320; c += NTHR){
      float s = 0.f;
      for (int j = 0; j < 256; j++) s = fmaf(bq[j], Wkv[(size_t)j*320 + c], s);
      g_aux[256 + c] = s;
    }
  } else if (bid == 42 && tid == 0){
    float s = 0.f;
    for (int j = 0; j < 256; j++) s = fmaf(bq[j], bkv[j], s);
    g_aux[576] = s;
  }
  grid_barrier();

  // ========== stage B: attn prep + qke partials (split-K 2) ===================
  if (tid == 0) s_cnt = 0;
  if (tid < 12) s_ax[tid/3][tid%3] = anchor_x[(size_t)(a0 + tid/3)*3 + (tid%3)];
  __syncthreads();
  {
    const int n = tid, ng = nbase + n;
    const float x0 = node_x[(size_t)3*ng+0];
    const float x1 = node_x[(size_t)3*ng+1];
    const float x2 = node_x[(size_t)3*ng+2];
#pragma unroll
    for (int a=0;a<4;a++){
      float dx = s_ax[a][0]-x0+EPSF;
      float dy = s_ax[a][1]-x1+EPSF;
      float dz = s_ax[a][2]-x2+EPSF;
      s_dist[a][n] = sqrtf(dx*dx + dy*dy + dz*dz);
    }
    if (nmask[ng] == 0.0f){
      int p = atomicAdd(&s_cnt, 1);
      s_list[p] = n;
    }
  }
  if (warp < 4){
    const float* ar = afeat + (size_t)(a0 + warp)*H;
    float s = 0.f;
#pragma unroll
    for (int kk=0;kk<8;kk++) s = fmaf(ar[lane+kk*32], g_aux[lane+kk*32], s);
    s = warp_reduce_sum(s);
    if (lane == 0) s_qbk[warp] = s + g_aux[576];
  }
  __syncthreads();

  if (bid < 80){
    int z = bid/40, tt = bid%40, my = tt/5, nx = tt%5;
    gemm64<false,false,true,true>(afeat,256, nullptr,nullptr,
        g_wc,320, g_wc + 81920,
        g_qke + (size_t)z*163840, 320, my*64, nx*64, z*128, z*128+128, &su.g);
  }
  grid_barrier();

  // ========== stage C: attention ==============================================
  for (int i = tid; i < 4*NPER; i += NTHR)
    su.a.logit[i>>9][i & 511] = 0.f;
  __syncthreads();
  for (int i = tid; i < 4*320; i += NTHR){
    int r = i / 320, c = i - r*320;
    size_t idx = (size_t)(a0 + r)*320 + c;
    float v = g_qke[idx] + g_qke[163840 + idx] + g_aux[256 + c];
    if (c < 256) su.a.qk[r][c] = v; else su.a.qek[r][c-256] = v;
  }
  __syncthreads();

  {                                               // masked logits only
    const int cnt = s_cnt;
    const float mu0 = (float)lane * MU_STEP;
    const float mu1 = (float)(lane+32) * MU_STEP;
    for (int i = warp; i < cnt; i += 16){
      const int n = s_list[i], ng = nbase + n;
      const float4* nf4 = (const float4*)(nf + (size_t)ng*H);
      float4 u0 = nf4[lane], u1 = nf4[lane+32];
#pragma unroll
      for (int a=0;a<4;a++){
        float t2 = s_dist[a][n] * 0.1f;
        float z0 = (t2 - mu0)*INV_SIG, z1 = (t2 - mu1)*INV_SIG;
        float z0s = z0*z0, z1s = z1*z1;
        float acc = 0.f;
        if (z0s < 64.f) acc  = __expf(-z0s) * su.a.qek[a][lane];
        if (z1s < 64.f) acc += __expf(-z1s) * su.a.qek[a][lane+32];
        const float4* qa = (const float4*)su.a.qk[a];
        float4 q0 = qa[lane], q1 = qa[lane+32];
        acc = fmaf(u0.x,q0.x, fmaf(u0.y,q0.y, fmaf(u0.z,q0.z, fmaf(u0.w,q0.w, acc))));
        acc = fmaf(u1.x,q1.x, fmaf(u1.y,q1.y, fmaf(u1.z,q1.z, fmaf(u1.w,q1.w, acc))));
        acc = warp_reduce_sum(acc);
        if (lane == 0) su.a.logit[a][n] = (acc + s_qbk[a]) * (-INFM);
      }
    }
  }
  __syncthreads();

#pragma unroll
  for (int a=0;a<4;a++){                          // softmax over 512
    float l = su.a.logit[a][tid];
    float m = warp_reduce_max(l);
    if (lane == 0) s_red[warp] = m;
    __syncthreads();
    float mx = s_red[0];
#pragma unroll
    for (int k=1;k<16;k++) mx = fmaxf(mx, s_red[k]);
    float e = __expf(l - mx);
    float s = warp_reduce_sum(e);
    __syncthreads();
    if (lane == 0) s_red[warp] = s;
    __syncthreads();
    float sm = 0.f;
#pragma unroll
    for (int k=0;k<16;k++) sm += s_red[k];
    su.a.logit[a][tid] = e / sm;
    __syncthreads();
  }

  {                                               // C1: s[a][j] = sum attn*rbf
    const int a = tid >> 7, r = tid & 127, j = r >> 1, half = r & 1;
    const float mu = (float)j * MU_STEP;
    float acc = 0.f;
    const int nb0 = half * 256;
#pragma unroll 4
    for (int nn=0; nn<256; nn++){
      int n = nb0 + nn;
      float z = (s_dist[a][n]*0.1f - mu) * INV_SIG;
      float z2 = z*z;
      if (z2 < 60.f) acc = fmaf(su.a.logit[a][n], __expf(-z2), acc);
    }
    acc += __shfl_xor_sync(0xffffffffu, acc, 1);
    if (half == 0) g_cb[(size_t)(a0+a)*320 + 256 + j] = acc;
  }
  __syncthreads();

  {                                               // C2: n_tilde = attn @ nf
    const int gg = tid >> 8, c = tid & 255;
    float ac0=0.f, ac1=0.f, ac2=0.f, ac3=0.f;
    const float* base = nf + (size_t)(nbase + gg*256)*H + c;
    const int nb0 = gg*256;
    for (int nn=0;nn<256;nn++){
      float f = base[(size_t)nn*H];
      ac0 = fmaf(su.a.logit[0][nb0+nn], f, ac0);
      ac1 = fmaf(su.a.logit[1][nb0+nn], f, ac1);
      ac2 = fmaf(su.a.logit[2][nb0+nn], f, ac2);
      ac3 = fmaf(su.a.logit[3][nb0+nn], f, ac3);
    }
    __syncthreads();
    if (gg == 1){
      s_dist[0][c]=ac0; s_dist[1][c]=ac1; s_dist[2][c]=ac2; s_dist[3][c]=ac3;
    }
    __syncthreads();
    if (gg == 0){
      g_cb[(size_t)(a0+0)*320 + c] = ac0 + s_dist[0][c];
      g_cb[(size_t)(a0+1)*320 + c] = ac1 + s_dist[1][c];
      g_cb[(size_t)(a0+2)*320 + c] = ac2 + s_dist[2][c];
      g_cb[(size_t)(a0+3)*320 + c] = ac3 + s_dist[3][c];
    }
  }
  grid_barrier();

  // ========== stage D: upd partials (split-K 4) ================================
  {
    const int z = bid >> 5, tt = bid & 31, my = tt >> 2, nx = tt & 3;
    gemm64<false,false,false,false>(g_cb,320, nullptr,nullptr,
        Wkv + (size_t)256*320,320, nullptr,
        g_upd + (size_t)z*131072, 256, my*64, nx*64, z*80, z*80+80, &su.g);
  }
  grid_barrier();

  // ========== stage E: af = LN1(afeat + sum(upd) + bkv_v) ======================
  lnP<4>(afeat, g_upd, 131072, bkv + 256, ln1g, ln1b, g_af);
  grid_barrier();

  // ========== stage F: m1 partials (split-K 2) =================================
  {
    const int z = bid >> 6, tt = bid & 63, my = tt >> 3, nx = tt & 7;
    gemm64<false,false,false,false>(g_af,256, nullptr,nullptr, W1,256, nullptr,
        g_m1 + (size_t)z*262144, 512, my*64, nx*64, z*128, z*128+128, &su.g);
  }
  grid_barrier();

  // ========== stage G: m2 partials; A = relu(m1p0+m1p1+b1) on load ============
  {
    const int z = bid >> 6, tt = bid & 63, my = tt >> 3, nx = tt & 7;
    gemm64<false,true,false,false>(g_m1,512, g_m1 + 262144, b1,
        W2,512, nullptr,
        g_m2 + (size_t)z*262144, 512, my*64, nx*64, z*256, z*256+256, &su.g);
  }
  grid_barrier();

  // ========== stage H: m3 partials (split-K 4); A = relu(m2p0+m2p1+b2) ========
  {
    const int z = bid >> 5, tt = bid & 31, my = tt >> 2, nx = tt & 3;
    gemm64<false,true,false,false>(g_m2,512, g_m2 + 262144, b2,
        W3,512, nullptr,
        g_m3 + (size_t)z*131072, 256, my*64, nx*64, z*128, z*128+128, &su.g);
  }
  grid_barrier();

  // ========== stage I: out = LN2(af + sum(m3) + b3) ============================
  lnP<4>(g_af, g_m3, 131072, b3, ln2g, ln2b, out);
}

// ------------------------- launch ---------------------------------------------
extern "C" void kernel_launch(void* const* d_in, const int* in_sizes, int n_in,
                              void* d_out, int out_size)
{
  const float* anchor_x        = (const float*)d_in[0];
  const float* node_x          = (const float*)d_in[1];
  const float* anchor_features = (const float*)d_in[2];
  const float* node_features   = (const float*)d_in[3];
  const float* node_mask       = (const float*)d_in[6];
  const float* Wq              = (const float*)d_in[7];
  const float* bq              = (const float*)d_in[8];
  const float* Wkv             = (const float*)d_in[9];
  const float* bkv             = (const float*)d_in[10];
  const float* ln1_g           = (const float*)d_in[11];
  const float* ln1_b           = (const float*)d_in[12];
  const float* W1              = (const float*)d_in[13];
  const float* b1              = (const float*)d_in[14];
  const float* W2              = (const float*)d_in[15];
  const float* b2              = (const float*)d_in[16];
  const float* W3              = (const float*)d_in[17];
  const float* b3              = (const float*)d_in[18];
  const float* ln2_g           = (const float*)d_in[19];
  const float* ln2_b           = (const float*)d_in[20];
  float* out = (float*)d_out;

  mega<<<NBLK, NTHR>>>(anchor_x, node_x, anchor_features, node_features,
                       node_mask, Wq, bq, Wkv, bkv, ln1_g, ln1_b,
                       W1, b1, W2, b2, W3, b3, ln2_g, ln2_b, out);
}

// round 9
// speedup vs baseline: 1.7941x; 1.7941x over previous
#include <cuda_runtime.h>
#include <math.h>

#define NBLK 128
#define NTHR 512
#define H    256
#define HE   64
#define APER 64
#define NPER 512
#define EPSF 1e-8f
#define INFM 1000000.0f
#define MU_STEP (20.0f/63.0f)
#define INV_SIG (64.0f/20.0f)

// ------------------------- scratch (device globals) --------------------------
__device__ float g_wc [2*256*320];    // split-K partials
__device__ float g_aux[640];          // [0:256) wqbk, [256:576) biasc, [576] bq.bk
__device__ float g_qke[2*512*320];
__device__ float g_cb [512*320];      // [n_tilde | s]
__device__ float g_upd[4*512*256];
__device__ float g_af [512*256];
__device__ float g_m1 [2*512*512];
__device__ float g_m2 [2*512*512];
__device__ float g_m3 [4*512*256];

__device__ unsigned g_bar_count = 0;
__device__ unsigned g_bar_epoch = 0;

// ------------------------- reductions -----------------------------------------
__device__ __forceinline__ float warp_reduce_sum(float v){
#pragma unroll
  for (int o=16;o>0;o>>=1) v += __shfl_xor_sync(0xffffffffu, v, o);
  return v;
}
__device__ __forceinline__ float warp_reduce_max(float v){
#pragma unroll
  for (int o=16;o>0;o>>=1) v = fmaxf(v, __shfl_xor_sync(0xffffffffu, v, o));
  return v;
}

// Software grid barrier (all NBLK blocks co-resident: NBLK <= 148 SMs).
__device__ __forceinline__ void grid_barrier(){
  __syncthreads();
  if (threadIdx.x == 0){
    __threadfence();
    unsigned e = atomicAdd(&g_bar_epoch, 0u);
    unsigned prev = atomicAdd(&g_bar_count, 1u);
    if (prev == gridDim.x - 1){
      atomicExch(&g_bar_count, 0u);
      __threadfence();
      atomicAdd(&g_bar_epoch, 1u);
    } else {
      volatile unsigned* ep = (volatile unsigned*)&g_bar_epoch;
      while (*ep == e) { }
      __threadfence();
    }
  }
  __syncthreads();
}

// Named barrier: syncs one 256-thread half of the block independently.
__device__ __forceinline__ void half_sync(int half){
  asm volatile("bar.sync %0, 256;" :: "r"(1 + half) : "memory");
}

// ------------------------- shared memory ---------------------------------------
struct GemmSmem { float As[2][16][40]; float Bs[2][16][68]; };   // 13.8 KB
struct AttnA    { float qk[4][H]; float qek[4][HE]; float logit[4][NPER]; };
union  __align__(16) SU { GemmSmem g[2]; AttnA a; };             // 27.6 KB

// ------------------------- scalar GEMM tile 32x64, 256 threads/instance --------
// A_KM: A is K-major (A[k*lda+m]); else row-major.
// ASUM: A := relu(A + A2 + abias[k]) on load (fused partial-sum consumption).
// BSUM: B := B + B2 on load (K,N layout only).
template<bool A_KM, bool ASUM, bool B_KN, bool BSUM>
__device__ void gemm_tile(const float* __restrict__ A, int lda,
                          const float* __restrict__ A2,
                          const float* __restrict__ abias,
                          const float* __restrict__ B, int ldb,
                          const float* __restrict__ B2,
                          float* __restrict__ C, int ldc,
                          int m0, int n0, int kbeg, int kend,
                          GemmSmem* sm, int half)
{
  const int t = threadIdx.x & 255;
  const int tx = t & 15, ty = t >> 4;             // ty 0..15, 2 rows each

  bool a_act; int a_i0, a_i1;
  if (A_KM){ a_act = (t < 128); a_i0 = t >> 3; a_i1 = t & 7; }   // k-row, m-grp
  else     { a_act = (t < 128); a_i0 = t >> 2; a_i1 = t & 3; }   // m-row, k-grp
  int b_i0, b_i1;
  if (B_KN){ b_i0 = t >> 4; b_i1 = t & 15; }      // k-row, n-grp
  else     { b_i0 = t >> 2; b_i1 = t & 3;  }      // n-row, k-grp

  auto loadA = [&](int k0)->float4 {
    if (!a_act) return make_float4(0.f,0.f,0.f,0.f);
    if (A_KM) return *(const float4*)(A + (size_t)(k0 + a_i0)*lda + m0 + a_i1*4);
    const size_t o = (size_t)(m0 + a_i0)*lda + k0 + a_i1*4;
    float4 v = *(const float4*)(A + o);
    if (ASUM){
      float4 v2 = *(const float4*)(A2 + o);
      float4 vb = *(const float4*)(abias + k0 + a_i1*4);
      v.x = fmaxf(v.x+v2.x+vb.x, 0.f); v.y = fmaxf(v.y+v2.y+vb.y, 0.f);
      v.z = fmaxf(v.z+v2.z+vb.z, 0.f); v.w = fmaxf(v.w+v2.w+vb.w, 0.f);
    }
    return v;
  };
  auto loadB = [&](int k0)->float4 {
    if (B_KN){
      const size_t o = (size_t)(k0 + b_i0)*ldb + n0 + b_i1*4;
      float4 v = *(const float4*)(B + o);
      if (BSUM){
        float4 w = *(const float4*)(B2 + o);
        v.x+=w.x; v.y+=w.y; v.z+=w.z; v.w+=w.w;
      }
      return v;
    }
    return *(const float4*)(B + (size_t)(n0 + b_i0)*ldb + k0 + b_i1*4);
  };
  auto storeA = [&](int buf, float4 v){
    if (!a_act) return;
    if (A_KM) *(float4*)&sm->As[buf][a_i0][a_i1*4] = v;
    else {
      sm->As[buf][a_i1*4+0][a_i0] = v.x;
      sm->As[buf][a_i1*4+1][a_i0] = v.y;
      sm->As[buf][a_i1*4+2][a_i0] = v.z;
      sm->As[buf][a_i1*4+3][a_i0] = v.w;
    }
  };
  auto storeB = [&](int buf, float4 v){
    if (B_KN) *(float4*)&sm->Bs[buf][b_i0][b_i1*4] = v;
    else {
      sm->Bs[buf][b_i1*4+0][b_i0] = v.x;
      sm->Bs[buf][b_i1*4+1][b_i0] = v.y;
      sm->Bs[buf][b_i1*4+2][b_i0] = v.z;
      sm->Bs[buf][b_i1*4+3][b_i0] = v.w;
    }
  };

  float acc[2][4];
#pragma unroll
  for (int i=0;i<2;i++)
#pragma unroll
    for (int j=0;j<4;j++) acc[i][j] = 0.f;

  half_sync(half);
  storeA(0, loadA(kbeg));
  storeB(0, loadB(kbeg));
  half_sync(half);

  int buf = 0;
  for (int k0 = kbeg + 16; ; k0 += 16, buf ^= 1){
    const bool more = (k0 < kend);
    float4 pa, pb;
    if (more){ pa = loadA(k0); pb = loadB(k0); }
#pragma unroll
    for (int kk = 0; kk < 16; kk++){
      float4 bv = *(const float4*)&sm->Bs[buf][kk][tx*4];
      float a0 = sm->As[buf][kk][ty*2+0];
      float a1 = sm->As[buf][kk][ty*2+1];
      acc[0][0] = fmaf(a0, bv.x, acc[0][0]); acc[0][1] = fmaf(a0, bv.y, acc[0][1]);
      acc[0][2] = fmaf(a0, bv.z, acc[0][2]); acc[0][3] = fmaf(a0, bv.w, acc[0][3]);
      acc[1][0] = fmaf(a1, bv.x, acc[1][0]); acc[1][1] = fmaf(a1, bv.y, acc[1][1]);
      acc[1][2] = fmaf(a1, bv.z, acc[1][2]); acc[1][3] = fmaf(a1, bv.w, acc[1][3]);
    }
    if (!more) break;
    storeA(buf^1, pa);
    storeB(buf^1, pb);
    half_sync(half);
  }

#pragma unroll
  for (int i=0;i<2;i++){
    const int m = m0 + ty*2 + i;
    *(float4*)(C + (size_t)m*ldc + n0 + tx*4) =
        make_float4(acc[i][0], acc[i][1], acc[i][2], acc[i][3]);
  }
}

// ------------------------- residual + LN (4 rows/block, P partials) ------------
template<int P>
__device__ void lnP(const float* __restrict__ r,
                    const float* __restrict__ part, size_t pstride,
                    const float* __restrict__ bias,
                    const float* __restrict__ g, const float* __restrict__ b,
                    float* __restrict__ o)
{
  const int w = threadIdx.x >> 5, lane = threadIdx.x & 31;
  if (w >= 4) return;
  const size_t row = (size_t)blockIdx.x*4 + w;
  float v[8]; float s = 0.f;
#pragma unroll
  for (int i=0;i<8;i++){
    int c = lane + i*32;
    size_t idx = row*H + c;
    float x = r[idx] + bias[c];
#pragma unroll
    for (int p=0;p<P;p++) x += part[(size_t)p*pstride + idx];
    v[i] = x; s += x;
  }
  s = warp_reduce_sum(s);
  float mean = s * (1.f/H);
  float s2 = 0.f;
#pragma unroll
  for (int i=0;i<8;i++){ float d = v[i]-mean; s2 += d*d; }
  s2 = warp_reduce_sum(s2);
  float inv = rsqrtf(s2*(1.f/H) + 1e-5f);
#pragma unroll
  for (int i=0;i<8;i++){
    int c = lane + i*32;
    o[row*H+c] = (v[i]-mean)*inv*g[c] + b[c];
  }
}

// ------------------------- megakernel ------------------------------------------
__global__ __launch_bounds__(NTHR)
void mega(const float* __restrict__ anchor_x,
          const float* __restrict__ node_x,
          const float* __restrict__ afeat,
          const float* __restrict__ nf,
          const float* __restrict__ nmask,
          const float* __restrict__ Wq,  const float* __restrict__ bq,
          const float* __restrict__ Wkv, const float* __restrict__ bkv,
          const float* __restrict__ ln1g, const float* __restrict__ ln1b,
          const float* __restrict__ W1, const float* __restrict__ b1,
          const float* __restrict__ W2, const float* __restrict__ b2,
          const float* __restrict__ W3, const float* __restrict__ b3,
          const float* __restrict__ ln2g, const float* __restrict__ ln2b,
          float* __restrict__ out)
{
  __shared__ SU su;
  __shared__ __align__(16) float s_dist[4][NPER];
  __shared__ float s_ax[4][3];
  __shared__ float s_qbk[4];
  __shared__ int   s_list[NPER];
  __shared__ int   s_cnt;
  __shared__ float s_red[16];

  const int tid = threadIdx.x, bid = blockIdx.x;
  const int lane = tid & 31, warp = tid >> 5;
  const int half = tid >> 8;                       // 0 or 1
  GemmSmem* gs = &su.g[half];
  const int inst = bid*2 + half;                   // 0..255 tile instances
  const int a0 = bid*4;
  const int nbase = (a0 / APER) * NPER;

  // ========== stage A: wc partials (40 tiles x splitK2 = 80 inst) + aux ========
  if (bid < 40){
    int z = inst / 40, tt = inst % 40, my = tt / 5, nx = tt % 5;
    gemm_tile<true,false,true,false>(Wq,256, nullptr,nullptr, Wkv,320, nullptr,
        g_wc + (size_t)z*81920, 320, my*32, nx*64, z*128, z*128+128, gs, half);
  } else if (bid == 40){
    for (int i = tid; i < 256; i += NTHR){
      float s = 0.f;
      for (int j = 0; j < 256; j++) s = fmaf(Wq[(size_t)j*256 + i], bkv[j], s);
      g_aux[i] = s;
    }
  } else if (bid == 41){
    for (int c = tid; c < 320; c += NTHR){
      float s = 0.f;
      for (int j = 0; j < 256; j++) s = fmaf(bq[j], Wkv[(size_t)j*320 + c], s);
      g_aux[256 + c] = s;
    }
  } else if (bid == 42 && tid == 0){
    float s = 0.f;
    for (int j = 0; j < 256; j++) s = fmaf(bq[j], bkv[j], s);
    g_aux[576] = s;
  }
  grid_barrier();

  // ========== stage B: attn prep + qke partials (80 tiles x splitK2) ==========
  if (tid == 0) s_cnt = 0;
  if (tid < 12) s_ax[tid/3][tid%3] = anchor_x[(size_t)(a0 + tid/3)*3 + (tid%3)];
  __syncthreads();
  if (tid < NPER){
    const int n = tid, ng = nbase + n;
    const float x0 = node_x[(size_t)3*ng+0];
    const float x1 = node_x[(size_t)3*ng+1];
    const float x2 = node_x[(size_t)3*ng+2];
#pragma unroll
    for (int a=0;a<4;a++){
      float dx = s_ax[a][0]-x0+EPSF;
      float dy = s_ax[a][1]-x1+EPSF;
      float dz = s_ax[a][2]-x2+EPSF;
      s_dist[a][n] = sqrtf(dx*dx + dy*dy + dz*dz);
    }
    if (nmask[ng] == 0.0f){
      int p = atomicAdd(&s_cnt, 1);
      s_list[p] = n;
    }
  }
  if (warp < 4){
    const float* ar = afeat + (size_t)(a0 + warp)*H;
    float s = 0.f;
#pragma unroll
    for (int kk=0;kk<8;kk++) s = fmaf(ar[lane+kk*32], g_aux[lane+kk*32], s);
    s = warp_reduce_sum(s);
    if (lane == 0) s_qbk[warp] = s + g_aux[576];
  }
  __syncthreads();

  if (bid < 80){
    int z = inst / 80, tt = inst % 80, my = tt / 5, nx = tt % 5;
    gemm_tile<false,false,true,true>(afeat,256, nullptr,nullptr,
        g_wc,320, g_wc + 81920,
        g_qke + (size_t)z*163840, 320, my*32, nx*64, z*128, z*128+128, gs, half);
  }
  grid_barrier();

  // ========== stage C: attention ================================================
  for (int i = tid; i < 4*NPER; i += NTHR)
    su.a.logit[i>>9][i & 511] = 0.f;
  __syncthreads();
  for (int i = tid; i < 4*320; i += NTHR){
    int r = i / 320, c = i - r*320;
    size_t idx = (size_t)(a0 + r)*320 + c;
    float v = g_qke[idx] + g_qke[163840 + idx] + g_aux[256 + c];
    if (c < 256) su.a.qk[r][c] = v; else su.a.qek[r][c-256] = v;
  }
  __syncthreads();

  {                                               // masked logits only
    const int cnt = s_cnt;
    const float mu0 = (float)lane * MU_STEP;
    const float mu1 = (float)(lane+32) * MU_STEP;
    for (int i = warp; i < cnt; i += 16){
      const int n = s_list[i], ng = nbase + n;
      const float4* nf4 = (const float4*)(nf + (size_t)ng*H);
      float4 u0 = nf4[lane], u1 = nf4[lane+32];
#pragma unroll
      for (int a=0;a<4;a++){
        float t2 = s_dist[a][n] * 0.1f;
        float z0 = (t2 - mu0)*INV_SIG, z1 = (t2 - mu1)*INV_SIG;
        float z0s = z0*z0, z1s = z1*z1;
        float acc = 0.f;
        if (z0s < 64.f) acc  = __expf(-z0s) * su.a.qek[a][lane];
        if (z1s < 64.f) acc += __expf(-z1s) * su.a.qek[a][lane+32];
        const float4* qa = (const float4*)su.a.qk[a];
        float4 q0 = qa[lane], q1 = qa[lane+32];
        acc = fmaf(u0.x,q0.x, fmaf(u0.y,q0.y, fmaf(u0.z,q0.z, fmaf(u0.w,q0.w, acc))));
        acc = fmaf(u1.x,q1.x, fmaf(u1.y,q1.y, fmaf(u1.z,q1.z, fmaf(u1.w,q1.w, acc))));
        acc = warp_reduce_sum(acc);
        if (lane == 0) su.a.logit[a][n] = (acc + s_qbk[a]) * (-INFM);
      }
    }
  }
  __syncthreads();

#pragma unroll
  for (int a=0;a<4;a++){                          // softmax over 512
    float l = su.a.logit[a][tid];
    float m = warp_reduce_max(l);
    if (lane == 0) s_red[warp] = m;
    __syncthreads();
    float mx = s_red[0];
#pragma unroll
    for (int k=1;k<16;k++) mx = fmaxf(mx, s_red[k]);
    float e = __expf(l - mx);
    float s = warp_reduce_sum(e);
    __syncthreads();
    if (lane == 0) s_red[warp] = s;
    __syncthreads();
    float sm = 0.f;
#pragma unroll
    for (int k=0;k<16;k++) sm += s_red[k];
    su.a.logit[a][tid] = e / sm;
    __syncthreads();
  }

  {                                               // C1: s[a][j] = sum attn*rbf
    const int a = tid >> 7, r = tid & 127, j = r >> 1, hh = r & 1;
    const float mu = (float)j * MU_STEP;
    float acc = 0.f;
    const int nb0 = hh * 256;
#pragma unroll 4
    for (int nn=0; nn<256; nn++){
      int n = nb0 + nn;
      float z = (s_dist[a][n]*0.1f - mu) * INV_SIG;
      float z2 = z*z;
      if (z2 < 60.f) acc = fmaf(su.a.logit[a][n], __expf(-z2), acc);
    }
    acc += __shfl_xor_sync(0xffffffffu, acc, 1);
    if (hh == 0) g_cb[(size_t)(a0+a)*320 + 256 + j] = acc;
  }
  __syncthreads();

  {                                               // C2: n_tilde = attn @ nf
    const int gg = tid >> 8, c = tid & 255;
    float ac0=0.f, ac1=0.f, ac2=0.f, ac3=0.f;
    const float* base = nf + (size_t)(nbase + gg*256)*H + c;
    const int nb0 = gg*256;
    for (int nn=0;nn<256;nn++){
      float f = base[(size_t)nn*H];
      ac0 = fmaf(su.a.logit[0][nb0+nn], f, ac0);
      ac1 = fmaf(su.a.logit[1][nb0+nn], f, ac1);
      ac2 = fmaf(su.a.logit[2][nb0+nn], f, ac2);
      ac3 = fmaf(su.a.logit[3][nb0+nn], f, ac3);
    }
    __syncthreads();
    if (gg == 1){
      s_dist[0][c]=ac0; s_dist[1][c]=ac1; s_dist[2][c]=ac2; s_dist[3][c]=ac3;
    }
    __syncthreads();
    if (gg == 0){
      g_cb[(size_t)(a0+0)*320 + c] = ac0 + s_dist[0][c];
      g_cb[(size_t)(a0+1)*320 + c] = ac1 + s_dist[1][c];
      g_cb[(size_t)(a0+2)*320 + c] = ac2 + s_dist[2][c];
      g_cb[(size_t)(a0+3)*320 + c] = ac3 + s_dist[3][c];
    }
  }
  grid_barrier();

  // ========== stage D: upd partials (64 tiles x splitK4 = 256 inst) ============
  {
    const int z = inst >> 6, tt = inst & 63, my = tt >> 2, nx = tt & 3;
    gemm_tile<false,false,false,false>(g_cb,320, nullptr,nullptr,
        Wkv + (size_t)256*320,320, nullptr,
        g_upd + (size_t)z*131072, 256, my*32, nx*64, z*80, z*80+80, gs, half);
  }
  grid_barrier();

  // ========== stage E: af = LN1(afeat + sum4(upd) + bkv_v) =====================
  lnP<4>(afeat, g_upd, 131072, bkv + 256, ln1g, ln1b, g_af);
  grid_barrier();

  // ========== stage F: m1 partials (128 tiles x splitK2 = 256 inst) ============
  {
    const int z = inst >> 7, tt = inst & 127, my = tt >> 3, nx = tt & 7;
    gemm_tile<false,false,false,false>(g_af,256, nullptr,nullptr, W1,256, nullptr,
        g_m1 + (size_t)z*262144, 512, my*32, nx*64, z*128, z*128+128, gs, half);
  }
  grid_barrier();

  // ========== stage G: m2 partials; A = relu(m1p0+m1p1+b1) on load =============
  {
    const int z = inst >> 7, tt = inst & 127, my = tt >> 3, nx = tt & 7;
    gemm_tile<false,true,false,false>(g_m1,512, g_m1 + 262144, b1,
        W2,512, nullptr,
        g_m2 + (size_t)z*262144, 512, my*32, nx*64, z*256, z*256+256, gs, half);
  }
  grid_barrier();

  // ========== stage H: m3 partials (64 tiles x splitK4); A = relu(m2+b2) =======
  {
    const int z = inst >> 6, tt = inst & 63, my = tt >> 2, nx = tt & 3;
    gemm_tile<false,true,false,false>(g_m2,512, g_m2 + 262144, b2,
        W3,512, nullptr,
        g_m3 + (size_t)z*131072, 256, my*32, nx*64, z*128, z*128+128, gs, half);
  }
  grid_barrier();

  // ========== stage I: out = LN2(af + sum4(m3) + b3) ===========================
  lnP<4>(g_af, g_m3, 131072, b3, ln2g, ln2b, out);
}

// ------------------------- launch ----------------------------------------------
extern "C" void kernel_launch(void* const* d_in, const int* in_sizes, int n_in,
                              void* d_out, int out_size)
{
  const float* anchor_x        = (const float*)d_in[0];
  const float* node_x          = (const float*)d_in[1];
  const float* anchor_features = (const float*)d_in[2];
  const float* node_features   = (const float*)d_in[3];
  const float* node_mask       = (const float*)d_in[6];
  const float* Wq              = (const float*)d_in[7];
  const float* bq              = (const float*)d_in[8];
  const float* Wkv             = (const float*)d_in[9];
  const float* bkv             = (const float*)d_in[10];
  const float* ln1_g           = (const float*)d_in[11];
  const float* ln1_b           = (const float*)d_in[12];
  const float* W1              = (const float*)d_in[13];
  const float* b1              = (const float*)d_in[14];
  const float* W2              = (const float*)d_in[15];
  const float* b2              = (const float*)d_in[16];
  const float* W3              = (const float*)d_in[17];
  const float* b3              = (const float*)d_in[18];
  const float* ln2_g           = (const float*)d_in[19];
  const float* ln2_b           = (const float*)d_in[20];
  float* out = (float*)d_out;

  mega<<<NBLK, NTHR>>>(anchor_x, node_x, anchor_features, node_features,
                       node_mask, Wq, bq, Wkv, bkv, ln1_g, ln1_b,
                       W1, b1, W2, b2, W3, b3, ln2_g, ln2_b, out);
}

// round 10
// speedup vs baseline: 1.9209x; 1.0707x over previous
#include <cuda_runtime.h>
#include <math.h>

#define NBLK 128
#define NTHR 512
#define H    256
#define HE   64
#define APER 64
#define NPER 512
#define EPSF 1e-8f
#define INFM 1000000.0f
#define MU_STEP (20.0f/63.0f)
#define INV_SIG (64.0f/20.0f)

// ------------------------- scratch (device globals) --------------------------
__device__ float g_wc [2*256*320];    // split-K2 partials
__device__ float g_aux[640];          // [0:256) wqbk, [256:576) biasc, [576] bq.bk
__device__ float g_qke[4*512*320];    // split-K4 partials
__device__ float g_cb [512*320];      // [n_tilde | s]
__device__ float g_upd[4*512*256];    // split-K4
__device__ float g_af [512*256];
__device__ float g_m1 [4*512*512];    // split-K4
__device__ float g_m2 [4*512*512];    // split-K4
__device__ float g_m3 [8*512*256];    // split-K8

__device__ unsigned g_bar_count = 0;
__device__ unsigned g_bar_epoch = 0;

// ------------------------- reductions -----------------------------------------
__device__ __forceinline__ float warp_reduce_sum(float v){
#pragma unroll
  for (int o=16;o>0;o>>=1) v += __shfl_xor_sync(0xffffffffu, v, o);
  return v;
}
__device__ __forceinline__ float warp_reduce_max(float v){
#pragma unroll
  for (int o=16;o>0;o>>=1) v = fmaxf(v, __shfl_xor_sync(0xffffffffu, v, o));
  return v;
}

// Software grid barrier (all NBLK blocks co-resident: NBLK <= 148 SMs).
__device__ __forceinline__ void grid_barrier(){
  __syncthreads();
  if (threadIdx.x == 0){
    __threadfence();
    unsigned e = atomicAdd(&g_bar_epoch, 0u);
    unsigned prev = atomicAdd(&g_bar_count, 1u);
    if (prev == gridDim.x - 1){
      atomicExch(&g_bar_count, 0u);
      __threadfence();
      atomicAdd(&g_bar_epoch, 1u);
    } else {
      volatile unsigned* ep = (volatile unsigned*)&g_bar_epoch;
      while (*ep == e) { }
      __threadfence();
    }
  }
  __syncthreads();
}

// Named barrier: syncs one 256-thread half of the block independently.
__device__ __forceinline__ void half_sync(int half){
  asm volatile("bar.sync %0, 256;" :: "r"(1 + half) : "memory");
}

// ------------------------- shared memory ---------------------------------------
struct GemmSmem { float As[2][16][68]; float Bs[2][16][68]; };   // 17.4 KB
struct AttnA    { float qk[4][H]; float qek[4][HE]; float logit[4][NPER]; };
union  __align__(16) SU { GemmSmem g[2]; AttnA a; };             // 34.8 KB

// ------------------------- GEMM tile 64x64, 256 threads/instance, 4x4 regs -----
// A_KM : A is K-major (A[k*lda+m]); else row-major (A[m*lda+k]).
// APART: >0 -> A := relu(sum_{p<APART} A[p*astride] + abias[k]) on load.
// B_KN : B is (K,N) row-major; else (N,K) row-major (@W.T form).
// BPART: >1 -> B := sum of BPART partials (K,N layout only).
template<bool A_KM, int APART, bool B_KN, int BPART>
__device__ void gemm_tile(const float* __restrict__ A, int lda, size_t astride,
                          const float* __restrict__ abias,
                          const float* __restrict__ B, int ldb, size_t bstride,
                          float* __restrict__ C, int ldc,
                          int m0, int n0, int kbeg, int kend,
                          GemmSmem* sm, int half)
{
  const int t  = threadIdx.x & 255;
  const int tx = t & 15, ty = t >> 4;            // 16x16 thread grid, 4x4 each

  int a_i0, a_i1, b_i0, b_i1;
  if (A_KM){ a_i0 = t >> 4; a_i1 = t & 15; }     // k-row(16), m-grp(16)
  else     { a_i0 = t >> 2; a_i1 = t & 3;  }     // m-row(64), k-grp(4)
  if (B_KN){ b_i0 = t >> 4; b_i1 = t & 15; }     // k-row(16), n-grp(16)
  else     { b_i0 = t >> 2; b_i1 = t & 3;  }     // n-row(64), k-grp(4)

  auto loadA = [&](int k0)->float4 {
    if (A_KM)
      return *(const float4*)(A + (size_t)(k0 + a_i0)*lda + m0 + a_i1*4);
    const size_t o = (size_t)(m0 + a_i0)*lda + k0 + a_i1*4;
    if (APART == 0) return *(const float4*)(A + o);
    float4 v = *(const float4*)(A + o);
#pragma unroll
    for (int p = 1; p < APART; p++){
      float4 w = *(const float4*)(A + p*astride + o);
      v.x+=w.x; v.y+=w.y; v.z+=w.z; v.w+=w.w;
    }
    float4 vb = *(const float4*)(abias + k0 + a_i1*4);
    v.x = fmaxf(v.x+vb.x, 0.f); v.y = fmaxf(v.y+vb.y, 0.f);
    v.z = fmaxf(v.z+vb.z, 0.f); v.w = fmaxf(v.w+vb.w, 0.f);
    return v;
  };
  auto loadB = [&](int k0)->float4 {
    if (B_KN){
      const size_t o = (size_t)(k0 + b_i0)*ldb + n0 + b_i1*4;
      float4 v = *(const float4*)(B + o);
#pragma unroll
      for (int p = 1; p < BPART; p++){
        float4 w = *(const float4*)(B + p*bstride + o);
        v.x+=w.x; v.y+=w.y; v.z+=w.z; v.w+=w.w;
      }
      return v;
    }
    return *(const float4*)(B + (size_t)(n0 + b_i0)*ldb + k0 + b_i1*4);
  };
  auto storeA = [&](int buf, float4 v){
    if (A_KM) *(float4*)&sm->As[buf][a_i0][a_i1*4] = v;
    else {
      sm->As[buf][a_i1*4+0][a_i0] = v.x;
      sm->As[buf][a_i1*4+1][a_i0] = v.y;
      sm->As[buf][a_i1*4+2][a_i0] = v.z;
      sm->As[buf][a_i1*4+3][a_i0] = v.w;
    }
  };
  auto storeB = [&](int buf, float4 v){
    if (B_KN) *(float4*)&sm->Bs[buf][b_i0][b_i1*4] = v;
    else {
      sm->Bs[buf][b_i1*4+0][b_i0] = v.x;
      sm->Bs[buf][b_i1*4+1][b_i0] = v.y;
      sm->Bs[buf][b_i1*4+2][b_i0] = v.z;
      sm->Bs[buf][b_i1*4+3][b_i0] = v.w;
    }
  };

  float acc[4][4];
#pragma unroll
  for (int i=0;i<4;i++)
#pragma unroll
    for (int j=0;j<4;j++) acc[i][j] = 0.f;

  half_sync(half);                       // protect smem reuse across stages
  storeA(0, loadA(kbeg));
  storeB(0, loadB(kbeg));
  half_sync(half);

  int buf = 0;
  for (int k0 = kbeg + 16; ; k0 += 16, buf ^= 1){
    const bool more = (k0 < kend);
    float4 pa, pb;
    if (more){ pa = loadA(k0); pb = loadB(k0); }
#pragma unroll
    for (int kk = 0; kk < 16; kk++){
      float4 av = *(const float4*)&sm->As[buf][kk][ty*4];
      float4 bv = *(const float4*)&sm->Bs[buf][kk][tx*4];
      acc[0][0] = fmaf(av.x, bv.x, acc[0][0]); acc[0][1] = fmaf(av.x, bv.y, acc[0][1]);
      acc[0][2] = fmaf(av.x, bv.z, acc[0][2]); acc[0][3] = fmaf(av.x, bv.w, acc[0][3]);
      acc[1][0] = fmaf(av.y, bv.x, acc[1][0]); acc[1][1] = fmaf(av.y, bv.y, acc[1][1]);
      acc[1][2] = fmaf(av.y, bv.z, acc[1][2]); acc[1][3] = fmaf(av.y, bv.w, acc[1][3]);
      acc[2][0] = fmaf(av.z, bv.x, acc[2][0]); acc[2][1] = fmaf(av.z, bv.y, acc[2][1]);
      acc[2][2] = fmaf(av.z, bv.z, acc[2][2]); acc[2][3] = fmaf(av.z, bv.w, acc[2][3]);
      acc[3][0] = fmaf(av.w, bv.x, acc[3][0]); acc[3][1] = fmaf(av.w, bv.y, acc[3][1]);
      acc[3][2] = fmaf(av.w, bv.z, acc[3][2]); acc[3][3] = fmaf(av.w, bv.w, acc[3][3]);
    }
    if (!more) break;
    storeA(buf^1, pa);
    storeB(buf^1, pb);
    half_sync(half);
  }

#pragma unroll
  for (int i=0;i<4;i++){
    const int m = m0 + ty*4 + i;
    *(float4*)(C + (size_t)m*ldc + n0 + tx*4) =
        make_float4(acc[i][0], acc[i][1], acc[i][2], acc[i][3]);
  }
}

// ------------------------- residual + LN (4 rows/block, P partials) ------------
template<int P>
__device__ void lnP(const float* __restrict__ r,
                    const float* __restrict__ part, size_t pstride,
                    const float* __restrict__ bias,
                    const float* __restrict__ g, const float* __restrict__ b,
                    float* __restrict__ o)
{
  const int w = threadIdx.x >> 5, lane = threadIdx.x & 31;
  if (w >= 4) return;
  const size_t row = (size_t)blockIdx.x*4 + w;
  float v[8]; float s = 0.f;
#pragma unroll
  for (int i=0;i<8;i++){
    int c = lane + i*32;
    size_t idx = row*H + c;
    float x = r[idx] + bias[c];
#pragma unroll
    for (int p=0;p<P;p++) x += part[(size_t)p*pstride + idx];
    v[i] = x; s += x;
  }
  s = warp_reduce_sum(s);
  float mean = s * (1.f/H);
  float s2 = 0.f;
#pragma unroll
  for (int i=0;i<8;i++){ float d = v[i]-mean; s2 += d*d; }
  s2 = warp_reduce_sum(s2);
  float inv = rsqrtf(s2*(1.f/H) + 1e-5f);
#pragma unroll
  for (int i=0;i<8;i++){
    int c = lane + i*32;
    o[row*H+c] = (v[i]-mean)*inv*g[c] + b[c];
  }
}

// ------------------------- megakernel ------------------------------------------
__global__ __launch_bounds__(NTHR)
void mega(const float* __restrict__ anchor_x,
          const float* __restrict__ node_x,
          const float* __restrict__ afeat,
          const float* __restrict__ nf,
          const float* __restrict__ nmask,
          const float* __restrict__ Wq,  const float* __restrict__ bq,
          const float* __restrict__ Wkv, const float* __restrict__ bkv,
          const float* __restrict__ ln1g, const float* __restrict__ ln1b,
          const float* __restrict__ W1, const float* __restrict__ b1,
          const float* __restrict__ W2, const float* __restrict__ b2,
          const float* __restrict__ W3, const float* __restrict__ b3,
          const float* __restrict__ ln2g, const float* __restrict__ ln2b,
          float* __restrict__ out)
{
  __shared__ SU su;
  __shared__ __align__(16) float s_dist[4][NPER];
  __shared__ float s_ax[4][3];
  __shared__ float s_qbk[4];
  __shared__ int   s_list[NPER];
  __shared__ int   s_cnt;
  __shared__ float s_red[16];

  const int tid = threadIdx.x, bid = blockIdx.x;
  const int lane = tid & 31, warp = tid >> 5;
  const int half = tid >> 8;                       // 0 or 1
  GemmSmem* gs = &su.g[half];
  const int inst = bid*2 + half;                   // 0..255 tile instances
  const int a0 = bid*4;
  const int nbase = (a0 / APER) * NPER;

  // ========== stage A: wc partials (20 tiles x splitK2 = 40 inst) + aux ========
  if (bid < 20){
    int z = inst / 20, tt = inst % 20, my = tt / 5, nx = tt % 5;
    gemm_tile<true,0,true,1>(Wq,256,0, nullptr, Wkv,320,0,
        g_wc + (size_t)z*81920, 320, my*64, nx*64, z*128, z*128+128, gs, half);
  } else if (bid == 40){
    for (int i = tid; i < 256; i += NTHR){
      float s = 0.f;
      for (int j = 0; j < 256; j++) s = fmaf(Wq[(size_t)j*256 + i], bkv[j], s);
      g_aux[i] = s;
    }
  } else if (bid == 41){
    for (int c = tid; c < 320; c += NTHR){
      float s = 0.f;
      for (int j = 0; j < 256; j++) s = fmaf(bq[j], Wkv[(size_t)j*320 + c], s);
      g_aux[256 + c] = s;
    }
  } else if (bid == 42 && tid == 0){
    float s = 0.f;
    for (int j = 0; j < 256; j++) s = fmaf(bq[j], bkv[j], s);
    g_aux[576] = s;
  }
  grid_barrier();

  // ========== stage B: attn prep + qke partials (40 tiles x splitK4) ==========
  if (tid == 0) s_cnt = 0;
  if (tid < 12) s_ax[tid/3][tid%3] = anchor_x[(size_t)(a0 + tid/3)*3 + (tid%3)];
  __syncthreads();
  if (tid < NPER){
    const int n = tid, ng = nbase + n;
    const float x0 = node_x[(size_t)3*ng+0];
    const float x1 = node_x[(size_t)3*ng+1];
    const float x2 = node_x[(size_t)3*ng+2];
#pragma unroll
    for (int a=0;a<4;a++){
      float dx = s_ax[a][0]-x0+EPSF;
      float dy = s_ax[a][1]-x1+EPSF;
      float dz = s_ax[a][2]-x2+EPSF;
      s_dist[a][n] = sqrtf(dx*dx + dy*dy + dz*dz);
    }
    if (nmask[ng] == 0.0f){
      int p = atomicAdd(&s_cnt, 1);
      s_list[p] = n;
    }
  }
  if (warp < 4){
    const float* ar = afeat + (size_t)(a0 + warp)*H;
    float s = 0.f;
#pragma unroll
    for (int kk=0;kk<8;kk++) s = fmaf(ar[lane+kk*32], g_aux[lane+kk*32], s);
    s = warp_reduce_sum(s);
    if (lane == 0) s_qbk[warp] = s + g_aux[576];
  }
  __syncthreads();

  if (bid < 80){
    int z = inst / 40, tt = inst % 40, my = tt / 5, nx = tt % 5;
    gemm_tile<false,0,true,2>(afeat,256,0, nullptr,
        g_wc,320,81920,
        g_qke + (size_t)z*163840, 320, my*64, nx*64, z*64, z*64+64, gs, half);
  }
  grid_barrier();

  // ========== stage C: attention ================================================
  for (int i = tid; i < 4*NPER; i += NTHR)
    su.a.logit[i>>9][i & 511] = 0.f;
  __syncthreads();
  for (int i = tid; i < 4*320; i += NTHR){
    int r = i / 320, c = i - r*320;
    size_t idx = (size_t)(a0 + r)*320 + c;
    float v = g_qke[idx] + g_qke[163840 + idx] + g_qke[2*163840 + idx]
            + g_qke[3*163840 + idx] + g_aux[256 + c];
    if (c < 256) su.a.qk[r][c] = v; else su.a.qek[r][c-256] = v;
  }
  __syncthreads();

  {                                               // masked logits only
    const int cnt = s_cnt;
    const float mu0 = (float)lane * MU_STEP;
    const float mu1 = (float)(lane+32) * MU_STEP;
    for (int i = warp; i < cnt; i += 16){
      const int n = s_list[i], ng = nbase + n;
      const float4* nf4 = (const float4*)(nf + (size_t)ng*H);
      float4 u0 = nf4[lane], u1 = nf4[lane+32];
#pragma unroll
      for (int a=0;a<4;a++){
        float t2 = s_dist[a][n] * 0.1f;
        float z0 = (t2 - mu0)*INV_SIG, z1 = (t2 - mu1)*INV_SIG;
        float z0s = z0*z0, z1s = z1*z1;
        float acc = 0.f;
        if (z0s < 64.f) acc  = __expf(-z0s) * su.a.qek[a][lane];
        if (z1s < 64.f) acc += __expf(-z1s) * su.a.qek[a][lane+32];
        const float4* qa = (const float4*)su.a.qk[a];
        float4 q0 = qa[lane], q1 = qa[lane+32];
        acc = fmaf(u0.x,q0.x, fmaf(u0.y,q0.y, fmaf(u0.z,q0.z, fmaf(u0.w,q0.w, acc))));
        acc = fmaf(u1.x,q1.x, fmaf(u1.y,q1.y, fmaf(u1.z,q1.z, fmaf(u1.w,q1.w, acc))));
        acc = warp_reduce_sum(acc);
        if (lane == 0) su.a.logit[a][n] = (acc + s_qbk[a]) * (-INFM);
      }
    }
  }
  __syncthreads();

#pragma unroll
  for (int a=0;a<4;a++){                          // softmax over 512
    float l = su.a.logit[a][tid];
    float m = warp_reduce_max(l);
    if (lane == 0) s_red[warp] = m;
    __syncthreads();
    float mx = s_red[0];
#pragma unroll
    for (int k=1;k<16;k++) mx = fmaxf(mx, s_red[k]);
    float e = __expf(l - mx);
    float s = warp_reduce_sum(e);
    __syncthreads();
    if (lane == 0) s_red[warp] = s;
    __syncthreads();
    float sm = 0.f;
#pragma unroll
    for (int k=0;k<16;k++) sm += s_red[k];
    su.a.logit[a][tid] = e / sm;
    __syncthreads();
  }

  {                                               // C1: s[a][j] = sum attn*rbf
    const int a = tid >> 7, r = tid & 127, j = r >> 1, hh = r & 1;
    const float mu = (float)j * MU_STEP;
    float acc = 0.f;
    const int nb0 = hh * 256;
#pragma unroll 4
    for (int nn=0; nn<256; nn++){
      int n = nb0 + nn;
      float z = (s_dist[a][n]*0.1f - mu) * INV_SIG;
      float z2 = z*z;
      if (z2 < 60.f) acc = fmaf(su.a.logit[a][n], __expf(-z2), acc);
    }
    acc += __shfl_xor_sync(0xffffffffu, acc, 1);
    if (hh == 0) g_cb[(size_t)(a0+a)*320 + 256 + j] = acc;
  }
  __syncthreads();

  {                                               // C2: n_tilde = attn @ nf
    const int gg = tid >> 8, c = tid & 255;
    float ac0=0.f, ac1=0.f, ac2=0.f, ac3=0.f;
    const float* base = nf + (size_t)(nbase + gg*256)*H + c;
    const int nb0 = gg*256;
    for (int nn=0;nn<256;nn++){
      float f = base[(size_t)nn*H];
      ac0 = fmaf(su.a.logit[0][nb0+nn], f, ac0);
      ac1 = fmaf(su.a.logit[1][nb0+nn], f, ac1);
      ac2 = fmaf(su.a.logit[2][nb0+nn], f, ac2);
      ac3 = fmaf(su.a.logit[3][nb0+nn], f, ac3);
    }
    __syncthreads();
    if (gg == 1){
      s_dist[0][c]=ac0; s_dist[1][c]=ac1; s_dist[2][c]=ac2; s_dist[3][c]=ac3;
    }
    __syncthreads();
    if (gg == 0){
      g_cb[(size_t)(a0+0)*320 + c] = ac0 + s_dist[0][c];
      g_cb[(size_t)(a0+1)*320 + c] = ac1 + s_dist[1][c];
      g_cb[(size_t)(a0+2)*320 + c] = ac2 + s_dist[2][c];
      g_cb[(size_t)(a0+3)*320 + c] = ac3 + s_dist[3][c];
    }
  }
  grid_barrier();

  // ========== stage D: upd partials (32 tiles x splitK4 = 128 inst) ============
  if (bid < 64){
    const int z = inst >> 5, tt = inst & 31, my = tt >> 2, nx = tt & 3;
    gemm_tile<false,0,false,1>(g_cb,320,0, nullptr,
        Wkv + (size_t)256*320,320,0,
        g_upd + (size_t)z*131072, 256, my*64, nx*64, z*80, z*80+80, gs, half);
  }
  grid_barrier();

  // ========== stage E: af = LN1(afeat + sum4(upd) + bkv_v) =====================
  lnP<4>(afeat, g_upd, 131072, bkv + 256, ln1g, ln1b, g_af);
  grid_barrier();

  // ========== stage F: m1 partials (64 tiles x splitK4 = 256 inst) =============
  {
    const int z = inst >> 6, tt = inst & 63, my = tt >> 3, nx = tt & 7;
    gemm_tile<false,0,false,1>(g_af,256,0, nullptr, W1,256,0,
        g_m1 + (size_t)z*262144, 512, my*64, nx*64, z*64, z*64+64, gs, half);
  }
  grid_barrier();

  // ========== stage G: m2 partials; A = relu(sum4(m1)+b1) on load ==============
  {
    const int z = inst >> 6, tt = inst & 63, my = tt >> 3, nx = tt & 7;
    gemm_tile<false,4,false,1>(g_m1,512,262144, b1, W2,512,0,
        g_m2 + (size_t)z*262144, 512, my*64, nx*64, z*128, z*128+128, gs, half);
  }
  grid_barrier();

  // ========== stage H: m3 partials (32 tiles x splitK8); A = relu(sum4(m2)+b2) =
  {
    const int z = inst >> 5, tt = inst & 31, my = tt >> 2, nx = tt & 3;
    gemm_tile<false,4,false,1>(g_m2,512,262144, b2, W3,512,0,
        g_m3 + (size_t)z*131072, 256, my*64, nx*64, z*64, z*64+64, gs, half);
  }
  grid_barrier();

  // ========== stage I: out = LN2(af + sum8(m3) + b3) ===========================
  lnP<8>(g_af, g_m3, 131072, b3, ln2g, ln2b, out);
}

// ------------------------- launch ----------------------------------------------
extern "C" void kernel_launch(void* const* d_in, const int* in_sizes, int n_in,
                              void* d_out, int out_size)
{
  const float* anchor_x        = (const float*)d_in[0];
  const float* node_x          = (const float*)d_in[1];
  const float* anchor_features = (const float*)d_in[2];
  const float* node_features   = (const float*)d_in[3];
  const float* node_mask       = (const float*)d_in[6];
  const float* Wq              = (const float*)d_in[7];
  const float* bq              = (const float*)d_in[8];
  const float* Wkv             = (const float*)d_in[9];
  const float* bkv             = (const float*)d_in[10];
  const float* ln1_g           = (const float*)d_in[11];
  const float* ln1_b           = (const float*)d_in[12];
  const float* W1              = (const float*)d_in[13];
  const float* b1              = (const float*)d_in[14];
  const float* W2              = (const float*)d_in[15];
  const float* b2              = (const float*)d_in[16];
  const float* W3              = (const float*)d_in[17];
  const float* b3              = (const float*)d_in[18];
  const float* ln2_g           = (const float*)d_in[19];
  const float* ln2_b           = (const float*)d_in[20];
  float* out = (float*)d_out;

  mega<<<NBLK, NTHR>>>(anchor_x, node_x, anchor_features, node_features,
                       node_mask, Wq, bq, Wkv, bkv, ln1_g, ln1_b,
                       W1, b1, W2, b2, W3, b3, ln2_g, ln2_b, out);
}

// round 11
// speedup vs baseline: 2.0437x; 1.0640x over previous
#include <cuda_runtime.h>
#include <math.h>

#define NBLK 128
#define NTHR 512
#define H    256
#define HE   64
#define APER 64
#define NPER 512
#define EPSF 1e-8f
#define INFM 1000000.0f
#define MU_STEP (20.0f/63.0f)
#define INV_SIG (64.0f/20.0f)

typedef unsigned long long u64;

// ------------------------- scratch (device globals) --------------------------
__device__ float g_wc [8*256*320];    // split-K8 partials
__device__ float g_aux[640];          // [0:256) wqbk, [256:576) biasc, [576] bq.bk
__device__ float g_qke[4*512*320];    // split-K4 partials
__device__ float g_cb [512*320];      // [n_tilde | s]
__device__ float g_upd[5*512*256];    // split-K5
__device__ float g_af [512*256];
__device__ float g_m1 [4*512*512];    // split-K4
__device__ float g_m2 [4*512*512];    // split-K4
__device__ float g_m3 [8*512*256];    // split-K8

__device__ unsigned g_bar_count = 0;
__device__ unsigned g_bar_epoch = 0;

// ------------------------- f32x2 helpers ---------------------------------------
__device__ __forceinline__ void ffma2(u64 &d, u64 a, u64 b){
  asm("fma.rn.f32x2 %0, %1, %2, %0;" : "+l"(d) : "l"(a), "l"(b));
}
__device__ __forceinline__ u64 pack2(float x, float y){
  u64 r; asm("mov.b64 %0, {%1, %2};" : "=l"(r) : "f"(x), "f"(y)); return r;
}
__device__ __forceinline__ float2 unpack2(u64 v){
  float2 r; asm("mov.b64 {%0, %1}, %2;" : "=f"(r.x), "=f"(r.y) : "l"(v)); return r;
}

// ------------------------- reductions -----------------------------------------
__device__ __forceinline__ float warp_reduce_sum(float v){
#pragma unroll
  for (int o=16;o>0;o>>=1) v += __shfl_xor_sync(0xffffffffu, v, o);
  return v;
}
__device__ __forceinline__ float warp_reduce_max(float v){
#pragma unroll
  for (int o=16;o>0;o>>=1) v = fmaxf(v, __shfl_xor_sync(0xffffffffu, v, o));
  return v;
}

// Software grid barrier (all NBLK blocks co-resident: NBLK <= 148 SMs).
__device__ __forceinline__ void grid_barrier(){
  __syncthreads();
  if (threadIdx.x == 0){
    __threadfence();
    unsigned e = atomicAdd(&g_bar_epoch, 0u);
    unsigned prev = atomicAdd(&g_bar_count, 1u);
    if (prev == gridDim.x - 1){
      atomicExch(&g_bar_count, 0u);
      __threadfence();
      atomicAdd(&g_bar_epoch, 1u);
    } else {
      volatile unsigned* ep = (volatile unsigned*)&g_bar_epoch;
      while (*ep == e) { }
      __threadfence();
    }
  }
  __syncthreads();
}

// Named barrier: syncs one 256-thread half of the block independently.
__device__ __forceinline__ void half_sync(int half){
  asm volatile("bar.sync %0, 256;" :: "r"(1 + half) : "memory");
}

// ------------------------- shared memory ---------------------------------------
struct GemmSmem { float As[2][16][68]; float Bs[2][16][68]; };   // 17.4 KB
struct AttnA    { float qk[4][H]; float qek[4][HE]; float logit[4][NPER]; };
union  __align__(16) SU { GemmSmem g[2]; AttnA a; };             // 34.8 KB

// ------------------------- GEMM tile 64x64, 256 thr/instance, FFMA2 ------------
// A_KM : A is K-major (A[k*lda+m]); else row-major (A[m*lda+k]).
// APART: >0 -> A := relu(sum_{p<APART} A[p*astride] + abias[k]) on load.
// B_KN : B is (K,N) row-major; else (N,K) row-major (@W.T form).
// BPART: >1 -> B := sum of BPART partials (K,N layout only).
template<bool A_KM, int APART, bool B_KN, int BPART>
__device__ void gemm_tile(const float* __restrict__ A, int lda, size_t astride,
                          const float* __restrict__ abias,
                          const float* __restrict__ B, int ldb, size_t bstride,
                          float* __restrict__ C, int ldc,
                          int m0, int n0, int kbeg, int kend,
                          GemmSmem* sm, int half)
{
  const int t  = threadIdx.x & 255;
  const int tx = t & 15, ty = t >> 4;            // 16x16 thread grid, 4x4 each

  int a_i0, a_i1, b_i0, b_i1;
  if (A_KM){ a_i0 = t >> 4; a_i1 = t & 15; }     // k-row(16), m-grp(16)
  else     { a_i0 = t >> 2; a_i1 = t & 3;  }     // m-row(64), k-grp(4)
  if (B_KN){ b_i0 = t >> 4; b_i1 = t & 15; }     // k-row(16), n-grp(16)
  else     { b_i0 = t >> 2; b_i1 = t & 3;  }     // n-row(64), k-grp(4)

  auto loadA = [&](int k0)->float4 {
    if (A_KM)
      return *(const float4*)(A + (size_t)(k0 + a_i0)*lda + m0 + a_i1*4);
    const size_t o = (size_t)(m0 + a_i0)*lda + k0 + a_i1*4;
    if (APART == 0) return *(const float4*)(A + o);
    float4 v = *(const float4*)(A + o);
#pragma unroll
    for (int p = 1; p < APART; p++){
      float4 w = *(const float4*)(A + p*astride + o);
      v.x+=w.x; v.y+=w.y; v.z+=w.z; v.w+=w.w;
    }
    float4 vb = *(const float4*)(abias + k0 + a_i1*4);
    v.x = fmaxf(v.x+vb.x, 0.f); v.y = fmaxf(v.y+vb.y, 0.f);
    v.z = fmaxf(v.z+vb.z, 0.f); v.w = fmaxf(v.w+vb.w, 0.f);
    return v;
  };
  auto loadB = [&](int k0)->float4 {
    if (B_KN){
      const size_t o = (size_t)(k0 + b_i0)*ldb + n0 + b_i1*4;
      float4 v = *(const float4*)(B + o);
#pragma unroll
      for (int p = 1; p < BPART; p++){
        float4 w = *(const float4*)(B + p*bstride + o);
        v.x+=w.x; v.y+=w.y; v.z+=w.z; v.w+=w.w;
      }
      return v;
    }
    return *(const float4*)(B + (size_t)(n0 + b_i0)*ldb + k0 + b_i1*4);
  };
  auto storeA = [&](int buf, float4 v){
    if (A_KM) *(float4*)&sm->As[buf][a_i0][a_i1*4] = v;
    else {
      sm->As[buf][a_i1*4+0][a_i0] = v.x;
      sm->As[buf][a_i1*4+1][a_i0] = v.y;
      sm->As[buf][a_i1*4+2][a_i0] = v.z;
      sm->As[buf][a_i1*4+3][a_i0] = v.w;
    }
  };
  auto storeB = [&](int buf, float4 v){
    if (B_KN) *(float4*)&sm->Bs[buf][b_i0][b_i1*4] = v;
    else {
      sm->Bs[buf][b_i1*4+0][b_i0] = v.x;
      sm->Bs[buf][b_i1*4+1][b_i0] = v.y;
      sm->Bs[buf][b_i1*4+2][b_i0] = v.z;
      sm->Bs[buf][b_i1*4+3][b_i0] = v.w;
    }
  };

  // acc[p][n]: p=0 -> rows (m0+ty*4, m0+ty*4+1), p=1 -> rows +2,+3 (f32x2 pairs)
  u64 acc[2][4];
#pragma unroll
  for (int i=0;i<2;i++)
#pragma unroll
    for (int j=0;j<4;j++) acc[i][j] = 0ULL;

  half_sync(half);                       // protect smem reuse across stages
  storeA(0, loadA(kbeg));
  storeB(0, loadB(kbeg));
  half_sync(half);

  int buf = 0;
  for (int k0 = kbeg + 16; ; k0 += 16, buf ^= 1){
    const bool more = (k0 < kend);
    float4 pa, pb;
    if (more){ pa = loadA(k0); pb = loadB(k0); }
#pragma unroll
    for (int kk = 0; kk < 16; kk++){
      ulonglong2 aa = *(const ulonglong2*)&sm->As[buf][kk][ty*4];
      float4 bv = *(const float4*)&sm->Bs[buf][kk][tx*4];
      u64 b0 = pack2(bv.x, bv.x), b1 = pack2(bv.y, bv.y);
      u64 b2 = pack2(bv.z, bv.z), b3 = pack2(bv.w, bv.w);
      ffma2(acc[0][0], aa.x, b0); ffma2(acc[0][1], aa.x, b1);
      ffma2(acc[0][2], aa.x, b2); ffma2(acc[0][3], aa.x, b3);
      ffma2(acc[1][0], aa.y, b0); ffma2(acc[1][1], aa.y, b1);
      ffma2(acc[1][2], aa.y, b2); ffma2(acc[1][3], aa.y, b3);
    }
    if (!more) break;
    storeA(buf^1, pa);
    storeB(buf^1, pb);
    half_sync(half);
  }

  float2 r0[4], r1[4];
#pragma unroll
  for (int j=0;j<4;j++){ r0[j] = unpack2(acc[0][j]); r1[j] = unpack2(acc[1][j]); }
  const int m = m0 + ty*4;
  *(float4*)(C + (size_t)(m+0)*ldc + n0 + tx*4) = make_float4(r0[0].x, r0[1].x, r0[2].x, r0[3].x);
  *(float4*)(C + (size_t)(m+1)*ldc + n0 + tx*4) = make_float4(r0[0].y, r0[1].y, r0[2].y, r0[3].y);
  *(float4*)(C + (size_t)(m+2)*ldc + n0 + tx*4) = make_float4(r1[0].x, r1[1].x, r1[2].x, r1[3].x);
  *(float4*)(C + (size_t)(m+3)*ldc + n0 + tx*4) = make_float4(r1[0].y, r1[1].y, r1[2].y, r1[3].y);
}

// ------------------------- residual + LN (4 rows/block, P partials) ------------
template<int P>
__device__ void lnP(const float* __restrict__ r,
                    const float* __restrict__ part, size_t pstride,
                    const float* __restrict__ bias,
                    const float* __restrict__ g, const float* __restrict__ b,
                    float* __restrict__ o)
{
  const int w = threadIdx.x >> 5, lane = threadIdx.x & 31;
  if (w >= 4) return;
  const size_t row = (size_t)blockIdx.x*4 + w;
  float v[8]; float s = 0.f;
#pragma unroll
  for (int i=0;i<8;i++){
    int c = lane + i*32;
    size_t idx = row*H + c;
    float x = r[idx] + bias[c];
#pragma unroll
    for (int p=0;p<P;p++) x += part[(size_t)p*pstride + idx];
    v[i] = x; s += x;
  }
  s = warp_reduce_sum(s);
  float mean = s * (1.f/H);
  float s2 = 0.f;
#pragma unroll
  for (int i=0;i<8;i++){ float d = v[i]-mean; s2 += d*d; }
  s2 = warp_reduce_sum(s2);
  float inv = rsqrtf(s2*(1.f/H) + 1e-5f);
#pragma unroll
  for (int i=0;i<8;i++){
    int c = lane + i*32;
    o[row*H+c] = (v[i]-mean)*inv*g[c] + b[c];
  }
}

// ------------------------- megakernel ------------------------------------------
__global__ __launch_bounds__(NTHR)
void mega(const float* __restrict__ anchor_x,
          const float* __restrict__ node_x,
          const float* __restrict__ afeat,
          const float* __restrict__ nf,
          const float* __restrict__ nmask,
          const float* __restrict__ Wq,  const float* __restrict__ bq,
          const float* __restrict__ Wkv, const float* __restrict__ bkv,
          const float* __restrict__ ln1g, const float* __restrict__ ln1b,
          const float* __restrict__ W1, const float* __restrict__ b1,
          const float* __restrict__ W2, const float* __restrict__ b2,
          const float* __restrict__ W3, const float* __restrict__ b3,
          const float* __restrict__ ln2g, const float* __restrict__ ln2b,
          float* __restrict__ out)
{
  __shared__ SU su;
  __shared__ __align__(16) float s_dist[4][NPER];
  __shared__ float s_ax[4][3];
  __shared__ float s_qbk[4];
  __shared__ int   s_list[NPER];
  __shared__ int   s_cnt;
  __shared__ float s_red[16];

  const int tid = threadIdx.x, bid = blockIdx.x;
  const int lane = tid & 31, warp = tid >> 5;
  const int half = tid >> 8;                       // 0 or 1
  GemmSmem* gs = &su.g[half];
  const int inst = bid*2 + half;                   // 0..255 tile instances
  const int a0 = bid*4;
  const int nbase = (a0 / APER) * NPER;

  // ========== stage A: wc partials (20 tiles x splitK8 = 160 inst) + aux =======
  if (bid < 80){
    int z = inst / 20, tt = inst % 20, my = tt / 5, nx = tt % 5;
    gemm_tile<true,0,true,1>(Wq,256,0, nullptr, Wkv,320,0,
        g_wc + (size_t)z*81920, 320, my*64, nx*64, z*32, z*32+32, gs, half);
  } else if (bid == 80){
    for (int i = tid; i < 256; i += NTHR){
      float s = 0.f;
      for (int j = 0; j < 256; j++) s = fmaf(Wq[(size_t)j*256 + i], bkv[j], s);
      g_aux[i] = s;
    }
  } else if (bid == 81){
    for (int c = tid; c < 320; c += NTHR){
      float s = 0.f;
      for (int j = 0; j < 256; j++) s = fmaf(bq[j], Wkv[(size_t)j*320 + c], s);
      g_aux[256 + c] = s;
    }
  } else if (bid == 82 && tid == 0){
    float s = 0.f;
    for (int j = 0; j < 256; j++) s = fmaf(bq[j], bkv[j], s);
    g_aux[576] = s;
  }
  grid_barrier();

  // ========== stage B: attn prep + qke partials (40 tiles x splitK4) ===========
  if (tid == 0) s_cnt = 0;
  if (tid < 12) s_ax[tid/3][tid%3] = anchor_x[(size_t)(a0 + tid/3)*3 + (tid%3)];
  __syncthreads();
  if (tid < NPER){
    const int n = tid, ng = nbase + n;
    const float x0 = node_x[(size_t)3*ng+0];
    const float x1 = node_x[(size_t)3*ng+1];
    const float x2 = node_x[(size_t)3*ng+2];
#pragma unroll
    for (int a=0;a<4;a++){
      float dx = s_ax[a][0]-x0+EPSF;
      float dy = s_ax[a][1]-x1+EPSF;
      float dz = s_ax[a][2]-x2+EPSF;
      s_dist[a][n] = sqrtf(dx*dx + dy*dy + dz*dz);
    }
    if (nmask[ng] == 0.0f){
      int p = atomicAdd(&s_cnt, 1);
      s_list[p] = n;
    }
  }
  if (warp < 4){
    const float* ar = afeat + (size_t)(a0 + warp)*H;
    float s = 0.f;
#pragma unroll
    for (int kk=0;kk<8;kk++) s = fmaf(ar[lane+kk*32], g_aux[lane+kk*32], s);
    s = warp_reduce_sum(s);
    if (lane == 0) s_qbk[warp] = s + g_aux[576];
  }
  __syncthreads();

  if (bid < 80){
    int z = inst / 40, tt = inst % 40, my = tt / 5, nx = tt % 5;
    gemm_tile<false,0,true,8>(afeat,256,0, nullptr,
        g_wc,320,81920,
        g_qke + (size_t)z*163840, 320, my*64, nx*64, z*64, z*64+64, gs, half);
  }
  grid_barrier();

  // ========== stage C: attention ================================================
  for (int i = tid; i < 4*NPER; i += NTHR)
    su.a.logit[i>>9][i & 511] = 0.f;
  __syncthreads();
  for (int i = tid; i < 4*320; i += NTHR){
    int r = i / 320, c = i - r*320;
    size_t idx = (size_t)(a0 + r)*320 + c;
    float v = g_qke[idx] + g_qke[163840 + idx] + g_qke[2*163840 + idx]
            + g_qke[3*163840 + idx] + g_aux[256 + c];
    if (c < 256) su.a.qk[r][c] = v; else su.a.qek[r][c-256] = v;
  }
  __syncthreads();

  {                                               // masked logits only
    const int cnt = s_cnt;
    const float mu0 = (float)lane * MU_STEP;
    const float mu1 = (float)(lane+32) * MU_STEP;
    for (int i = warp; i < cnt; i += 16){
      const int n = s_list[i], ng = nbase + n;
      const float4* nf4 = (const float4*)(nf + (size_t)ng*H);
      float4 u0 = nf4[lane], u1 = nf4[lane+32];
#pragma unroll
      for (int a=0;a<4;a++){
        float t2 = s_dist[a][n] * 0.1f;
        float z0 = (t2 - mu0)*INV_SIG, z1 = (t2 - mu1)*INV_SIG;
        float z0s = z0*z0, z1s = z1*z1;
        float acc = 0.f;
        if (z0s < 64.f) acc  = __expf(-z0s) * su.a.qek[a][lane];
        if (z1s < 64.f) acc += __expf(-z1s) * su.a.qek[a][lane+32];
        const float4* qa = (const float4*)su.a.qk[a];
        float4 q0 = qa[lane], q1 = qa[lane+32];
        acc = fmaf(u0.x,q0.x, fmaf(u0.y,q0.y, fmaf(u0.z,q0.z, fmaf(u0.w,q0.w, acc))));
        acc = fmaf(u1.x,q1.x, fmaf(u1.y,q1.y, fmaf(u1.z,q1.z, fmaf(u1.w,q1.w, acc))));
        acc = warp_reduce_sum(acc);
        if (lane == 0) su.a.logit[a][n] = (acc + s_qbk[a]) * (-INFM);
      }
    }
  }
  __syncthreads();

#pragma unroll
  for (int a=0;a<4;a++){                          // softmax over 512
    float l = su.a.logit[a][tid];
    float m = warp_reduce_max(l);
    if (lane == 0) s_red[warp] = m;
    __syncthreads();
    float mx = s_red[0];
#pragma unroll
    for (int k=1;k<16;k++) mx = fmaxf(mx, s_red[k]);
    float e = __expf(l - mx);
    float s = warp_reduce_sum(e);
    __syncthreads();
    if (lane == 0) s_red[warp] = s;
    __syncthreads();
    float sm = 0.f;
#pragma unroll
    for (int k=0;k<16;k++) sm += s_red[k];
    su.a.logit[a][tid] = e / sm;
    __syncthreads();
  }

  {                                               // C1: s[a][j] = sum attn*rbf
    const int a = tid >> 7, r = tid & 127, j = r >> 1, hh = r & 1;
    const float mu = (float)j * MU_STEP;
    float acc = 0.f;
    const int nb0 = hh * 256;
#pragma unroll 4
    for (int nn=0; nn<256; nn++){
      int n = nb0 + nn;
      float z = (s_dist[a][n]*0.1f - mu) * INV_SIG;
      float z2 = z*z;
      if (z2 < 60.f) acc = fmaf(su.a.logit[a][n], __expf(-z2), acc);
    }
    acc += __shfl_xor_sync(0xffffffffu, acc, 1);
    if (hh == 0) g_cb[(size_t)(a0+a)*320 + 256 + j] = acc;
  }
  __syncthreads();

  {                                               // C2: n_tilde = attn @ nf
    const int gg = tid >> 8, c = tid & 255;
    float ac0=0.f, ac1=0.f, ac2=0.f, ac3=0.f;
    const float* base = nf + (size_t)(nbase + gg*256)*H + c;
    const int nb0 = gg*256;
    for (int nn=0;nn<256;nn++){
      float f = base[(size_t)nn*H];
      ac0 = fmaf(su.a.logit[0][nb0+nn], f, ac0);
      ac1 = fmaf(su.a.logit[1][nb0+nn], f, ac1);
      ac2 = fmaf(su.a.logit[2][nb0+nn], f, ac2);
      ac3 = fmaf(su.a.logit[3][nb0+nn], f, ac3);
    }
    __syncthreads();
    if (gg == 1){
      s_dist[0][c]=ac0; s_dist[1][c]=ac1; s_dist[2][c]=ac2; s_dist[3][c]=ac3;
    }
    __syncthreads();
    if (gg == 0){
      g_cb[(size_t)(a0+0)*320 + c] = ac0 + s_dist[0][c];
      g_cb[(size_t)(a0+1)*320 + c] = ac1 + s_dist[1][c];
      g_cb[(size_t)(a0+2)*320 + c] = ac2 + s_dist[2][c];
      g_cb[(size_t)(a0+3)*320 + c] = ac3 + s_dist[3][c];
    }
  }
  grid_barrier();

  // ========== stage D: upd partials (32 tiles x splitK5 = 160 inst) ============
  if (bid < 80){
    const int z = inst >> 5, tt = inst & 31, my = tt >> 2, nx = tt & 3;
    gemm_tile<false,0,false,1>(g_cb,320,0, nullptr,
        Wkv + (size_t)256*320,320,0,
        g_upd + (size_t)z*131072, 256, my*64, nx*64, z*64, z*64+64, gs, half);
  }
  grid_barrier();

  // ========== stage E: af = LN1(afeat + sum5(upd) + bkv_v) =====================
  lnP<5>(afeat, g_upd, 131072, bkv + 256, ln1g, ln1b, g_af);
  grid_barrier();

  // ========== stage F: m1 partials (64 tiles x splitK4 = 256 inst) =============
  {
    const int z = inst >> 6, tt = inst & 63, my = tt >> 3, nx = tt & 7;
    gemm_tile<false,0,false,1>(g_af,256,0, nullptr, W1,256,0,
        g_m1 + (size_t)z*262144, 512, my*64, nx*64, z*64, z*64+64, gs, half);
  }
  grid_barrier();

  // ========== stage G: m2 partials; A = relu(sum4(m1)+b1) on load ==============
  {
    const int z = inst >> 6, tt = inst & 63, my = tt >> 3, nx = tt & 7;
    gemm_tile<false,4,false,1>(g_m1,512,262144, b1, W2,512,0,
        g_m2 + (size_t)z*262144, 512, my*64, nx*64, z*128, z*128+128, gs, half);
  }
  grid_barrier();

  // ========== stage H: m3 partials (32 tiles x splitK8); A = relu(sum4(m2)+b2) =
  {
    const int z = inst >> 5, tt = inst & 31, my = tt >> 2, nx = tt & 3;
    gemm_tile<false,4,false,1>(g_m2,512,262144, b2, W3,512,0,
        g_m3 + (size_t)z*131072, 256, my*64, nx*64, z*64, z*64+64, gs, half);
  }
  grid_barrier();

  // ========== stage I: out = LN2(af + sum8(m3) + b3) ===========================
  lnP<8>(g_af, g_m3, 131072, b3, ln2g, ln2b, out);
}

// ------------------------- launch ----------------------------------------------
extern "C" void kernel_launch(void* const* d_in, const int* in_sizes, int n_in,
                              void* d_out, int out_size)
{
  const float* anchor_x        = (const float*)d_in[0];
  const float* node_x          = (const float*)d_in[1];
  const float* anchor_features = (const float*)d_in[2];
  const float* node_features   = (const float*)d_in[3];
  const float* node_mask       = (const float*)d_in[6];
  const float* Wq              = (const float*)d_in[7];
  const float* bq              = (const float*)d_in[8];
  const float* Wkv             = (const float*)d_in[9];
  const float* bkv             = (const float*)d_in[10];
  const float* ln1_g           = (const float*)d_in[11];
  const float* ln1_b           = (const float*)d_in[12];
  const float* W1              = (const float*)d_in[13];
  const float* b1              = (const float*)d_in[14];
  const float* W2              = (const float*)d_in[15];
  const float* b2              = (const float*)d_in[16];
  const float* W3              = (const float*)d_in[17];
  const float* b3              = (const float*)d_in[18];
  const float* ln2_g           = (const float*)d_in[19];
  const float* ln2_b           = (const float*)d_in[20];
  float* out = (float*)d_out;

  mega<<<NBLK, NTHR>>>(anchor_x, node_x, anchor_features, node_features,
                       node_mask, Wq, bq, Wkv, bkv, ln1_g, ln1_b,
                       W1, b1, W2, b2, W3, b3, ln2_g, ln2_b, out);
}